// round 6
// baseline (speedup 1.0000x reference)
#include <cuda_runtime.h>
#include <cstdint>

#define B   32
#define H   384
#define W   640
#define C   128
#define HS  96      // H / SCALE
#define WS  160     // W / SCALE
#define FW  30
#define THRESH 0.015f
#define TOPK 2000
#define TBLOCKS 2048   // persistent transpose grid
#define CHUNK 4096     // pixels per select chunk (1024 thr * 4 px)
#define NF   8         // parallel select chunks (covers 32K px >> TOPK at >6% density)

// Static device scratch (allocation-free rule: __device__ globals allowed)
__device__ float d_hwc[(size_t)B * HS * WS * C];
__device__ int   d_idx[B * TOPK];     // ascending selected linear indices
__device__ int   d_count[B];          // number of valid entries (<= TOPK)

// ---------------------------------------------------------------------------
// Chunk emission helper: pixels [pixBase, pixBase+CHUNK) of batch b's
// in-region stream; hits get ordered rank base+local; ranks < TOPK emitted.
// Returns chunk hit count (valid in all threads). 1024 threads required.
// ---------------------------------------------------------------------------
__device__ __forceinline__ int emit_chunk(
    const float* __restrict__ pb, int rowW, int totalPix, int pixBase,
    int base, int b, float rv, float* __restrict__ pts_out,
    int* sWarpBase, int* sTotal)
{
    const int tid  = threadIdx.x;
    const int warp = tid >> 5;
    const int lane = tid & 31;

    unsigned pmask = 0;
    int rr[4], cc[4];
    const int pix0 = pixBase + 4 * tid;
    if (rowW > 0 && pix0 < totalPix) {
        const int rq = pix0 / rowW;
        int ri = FW + rq, ci = FW + pix0 - rq * rowW;
        #pragma unroll
        for (int j = 0; j < 4; ++j) {
            rr[j] = ri; cc[j] = ci;
            if ((pix0 + j) < totalPix && pb[(size_t)ri * W + ci] > THRESH)
                pmask |= (1u << j);
            if (++ci >= FW + rowW) { ci = FW; ++ri; }
        }
    }
    const int cnt = __popc(pmask);

    int incl = cnt;
    #pragma unroll
    for (int d = 1; d < 32; d <<= 1) {
        int y = __shfl_up_sync(0xffffffffu, incl, d);
        if (lane >= d) incl += y;
    }
    if (lane == 31) sWarpBase[warp] = incl;
    __syncthreads();
    if (tid < 32) {
        int v = sWarpBase[tid];
        int x = v;
        #pragma unroll
        for (int d = 1; d < 32; d <<= 1) {
            int y = __shfl_up_sync(0xffffffffu, x, d);
            if (tid >= d) x += y;
        }
        sWarpBase[tid] = x - v;
        if (tid == 31) *sTotal = x;
    }
    __syncthreads();
    int pos = base + sWarpBase[warp] + (incl - cnt);

    #pragma unroll
    for (int j = 0; j < 4; ++j) {
        if (pmask & (1u << j)) {
            if (pos < TOPK) {
                d_idx[b * TOPK + pos] = rr[j] * W + cc[j];
                ((float2*)pts_out)[(size_t)b * TOPK + pos] =
                    make_float2((float)cc[j] / rv, (float)rr[j] / rv);
            }
            ++pos;
        }
    }
    const int total = *sTotal;
    __syncthreads();   // protect shared scratch for the next call
    return total;
}

// ---------------------------------------------------------------------------
// Kernel 1: single-launch wide ordered selection. grid (B, NF), block 1024.
// Block ck derives its rank base by re-counting chunks 0..ck-1 (independent
// loads; chunks are L2-multicast across the <=8 blocks of a batch), then
// emits chunk ck. Block NF-1 also finishes serially past the fast region and
// writes d_count + the invalid tail.
// ---------------------------------------------------------------------------
__global__ __launch_bounds__(1024) void select_kernel(
    const float* __restrict__ prob,
    const float* __restrict__ ratio,
    const int* __restrict__ rshape_raw,
    float* __restrict__ pts_out)
{
    const int b   = blockIdx.x;
    const int ck  = blockIdx.y;
    const int tid = threadIdx.x;
    const int warp = tid >> 5;
    const int lane = tid & 31;

    __shared__ int sWarpBase[32];
    __shared__ int sTotal;
    __shared__ int sPre;

    // r_shape dtype sniff: int64 LE -> word 1 is high half of first value (0);
    // int32 -> word 1 is W != 0.
    const int stride = (rshape_raw[1] == 0) ? 2 : 1;
    const int r0 = rshape_raw[(2 * b)     * stride];
    const int r1 = rshape_raw[(2 * b + 1) * stride];
    const int rowW     = r1 - 2 * FW;
    const int totalPix = (r0 - 2 * FW) * rowW;
    const float rv = ratio[b];
    const float* pb = prob + (size_t)b * H * W;

    // count hits in chunks 0..ck-1 (loads across chunks are independent)
    int pre = 0;
    for (int j = 0; j < ck; ++j) {
        const int pix0 = j * CHUNK + 4 * tid;
        if (rowW > 0 && pix0 < totalPix) {
            const int rq = pix0 / rowW;
            int ri = FW + rq, ci = FW + pix0 - rq * rowW;
            #pragma unroll
            for (int jj = 0; jj < 4; ++jj) {
                if ((pix0 + jj) < totalPix && pb[(size_t)ri * W + ci] > THRESH) ++pre;
                if (++ci >= FW + rowW) { ci = FW; ++ri; }
            }
        }
    }
    // block reduction of pre
    #pragma unroll
    for (int d = 16; d > 0; d >>= 1)
        pre += __shfl_down_sync(0xffffffffu, pre, d);
    if (lane == 0) sWarpBase[warp] = pre;
    __syncthreads();
    if (tid < 32) {
        int v = sWarpBase[tid];
        #pragma unroll
        for (int d = 16; d > 0; d >>= 1)
            v += __shfl_down_sync(0xffffffffu, v, d);
        if (tid == 0) sPre = v;
    }
    __syncthreads();

    const int chunkStart = sPre;
    const bool finisher = (ck == NF - 1);
    if (!finisher && chunkStart >= TOPK) return;
    __syncthreads();   // sWarpBase reuse safety

    int base = chunkStart;
    if (chunkStart < TOPK) {
        base += emit_chunk(pb, rowW, totalPix, ck * CHUNK, chunkStart, b, rv,
                           pts_out, sWarpBase, &sTotal);
    }

    if (finisher) {
        if (chunkStart < TOPK) {
            for (int sw = NF * CHUNK; sw < totalPix && base < TOPK; sw += CHUNK) {
                base += emit_chunk(pb, rowW, totalPix, sw, base, b, rv,
                                   pts_out, sWarpBase, &sTotal);
            }
        }
        const int cnt = (base < TOPK) ? base : TOPK;
        if (tid == 0) d_count[b] = cnt;
        for (int k = cnt + tid; k < TOPK; k += 1024) {
            d_idx[b * TOPK + k] = -1;
            ((float2*)pts_out)[(size_t)b * TOPK + k] = make_float2(0.0f, 0.0f);
        }
    }
}

// ---------------------------------------------------------------------------
// Kernel 2: persistent CHW -> HWC transpose over a compact task list.
// Needed feat-row range per batch derived from the ascending d_idx stream:
// first valid index -> ymin, last valid -> ymax (+1 tap row, clamped).
// ---------------------------------------------------------------------------
__global__ __launch_bounds__(256) void transpose_kernel(const float* __restrict__ feat)
{
    __shared__ int sOff[B + 1];
    __shared__ int sYmin[B];
    __shared__ float tile[32][33];

    const int t0 = threadIdx.y * 32 + threadIdx.x;
    if (t0 == 0) {
        int acc = 0;
        #pragma unroll
        for (int b = 0; b < B; ++b) {
            const int cnt = d_count[b];
            int ymin = 0, n = 0;
            if (cnt > 0) {
                const int rFirst = d_idx[b * TOPK] / W;
                const int rLast  = d_idx[b * TOPK + cnt - 1] / W;
                ymin = rFirst >> 2;
                int ymaxr = (rLast >> 2) + 1;
                if (ymaxr > HS - 1) ymaxr = HS - 1;
                n = ymaxr - ymin + 1;
            }
            sOff[b] = acc;
            sYmin[b] = ymin;
            acc += n;
        }
        sOff[B] = acc;
    }
    __syncthreads();
    const int totalTasks = sOff[B] * 20;

    const int tx = threadIdx.x;  // 0..31
    const int ty = threadIdx.y;  // 0..7

    for (int t = blockIdx.x; t < totalTasks; t += TBLOCKS) {
        const int rowTask = t / 20;
        const int tileId  = t - rowTask * 20;
        int b = 0;
        while (sOff[b + 1] <= rowTask) ++b;        // uniform across block
        const int y  = sYmin[b] + (rowTask - sOff[b]);
        const int xt = tileId % 5;                 // 0..4 (x tiles of 32)
        const int ct = tileId / 5;                 // 0..3 (c tiles of 32)

        const float* src = feat + ((size_t)b * C) * (HS * WS) + (size_t)y * WS;
        #pragma unroll
        for (int i = 0; i < 4; ++i) {
            const int cc = ct * 32 + ty + i * 8;
            tile[ty + i * 8][tx] = src[(size_t)cc * (HS * WS) + xt * 32 + tx];
        }
        __syncthreads();
        float* dst = d_hwc + ((size_t)(b * HS + y) * WS) * C;
        #pragma unroll
        for (int i = 0; i < 4; ++i) {
            const int x = xt * 32 + ty + i * 8;
            dst[(size_t)x * C + ct * 32 + tx] = tile[tx][ty + i * 8];
        }
        __syncthreads();
    }
}

// ---------------------------------------------------------------------------
// Kernel 3: bilinear gather with shared point-decode.
// 256 threads = 8 point-lanes x 32 channel-groups; 32 points per block.
// Threads 0..31 decode each point ONCE (tap base offset in float4 units +
// weight vector) into smem; main loop is LDS + 4x LDG.128 + FFMA + STG.128.
// ---------------------------------------------------------------------------
__global__ __launch_bounds__(256) void gather_kernel(float* __restrict__ des_out)
{
    const int b  = blockIdx.y;
    const int p0 = blockIdx.x * 32;
    const int cg = threadIdx.x & 31;   // channel group (4 ch each)
    const int pl = threadIdx.x >> 5;   // point lane 0..7

    __shared__ int    sOff[32];
    __shared__ float4 sWt[32];
    if (threadIdx.x < 32) {
        const int p = p0 + threadIdx.x;
        const int lin = (p < TOPK) ? d_idx[b * TOPK + p] : -1;
        int off = -1;
        float4 wt = make_float4(0.f, 0.f, 0.f, 0.f);
        if (lin >= 0) {
            const int y = lin / W;
            const int x = lin - y * W;
            const int x0 = x >> 2;
            const int y0 = y >> 2;
            const float fx = (float)(x & 3) * 0.25f;
            const float fy = (float)(y & 3) * 0.25f;
            off = ((b * HS + y0) * WS + x0) * (C / 4);
            wt = make_float4((1.f - fx) * (1.f - fy),   // Ia (y0,x0)
                             (1.f - fx) * fy,           // Ib (y1,x0)
                             fx * (1.f - fy),           // Ic (y0,x1)
                             fx * fy);                  // Id (y1,x1)
        }
        sOff[threadIdx.x] = off;
        sWt[threadIdx.x]  = wt;
    }
    __syncthreads();

    const float4* hwc4 = (const float4*)d_hwc;
    #pragma unroll
    for (int i = 0; i < 4; ++i) {
        const int j = pl + i * 8;
        const int p = p0 + j;
        if (p >= TOPK) break;
        const int off = sOff[j];
        float4 v = make_float4(0.f, 0.f, 0.f, 0.f);
        if (off >= 0) {
            const float4 w = sWt[j];
            const float4* basep = hwc4 + off + cg;
            const float4 Ia = basep[0];                   // (y0,x0)
            const float4 Ic = basep[C / 4];               // (y0,x1)
            const float4 Ib = basep[WS * (C / 4)];        // (y1,x0)
            const float4 Id = basep[WS * (C / 4) + C / 4];// (y1,x1)
            v.x = Ia.x * w.x + Ib.x * w.y + Ic.x * w.z + Id.x * w.w;
            v.y = Ia.y * w.x + Ib.y * w.y + Ic.y * w.z + Id.y * w.w;
            v.z = Ia.z * w.x + Ib.z * w.y + Ic.z * w.z + Id.z * w.w;
            v.w = Ia.w * w.x + Ib.w * w.y + Ic.w * w.z + Id.w * w.w;
        }
        ((float4*)des_out)[((size_t)b * TOPK + p) * (C / 4) + cg] = v;
    }
}

// ---------------------------------------------------------------------------
extern "C" void kernel_launch(void* const* d_in, const int* in_sizes, int n_in,
                              void* d_out, int out_size)
{
    const float* prob   = (const float*)d_in[0];      // [B,1,H,W]
    const float* feat   = (const float*)d_in[1];      // [B,C,HS,WS]
    const float* ratio  = (const float*)d_in[2];      // [B,1]
    const int*   rshape = (const int*)d_in[3];        // [B,2] int32 (or int64-packed)

    float* pts_out = (float*)d_out;                        // [B,TOPK,2]
    float* des_out = (float*)d_out + (size_t)B * TOPK * 2; // [B,TOPK,C]

    select_kernel<<<dim3(B, NF), 1024>>>(prob, ratio, rshape, pts_out);
    transpose_kernel<<<TBLOCKS, dim3(32, 8)>>>(feat);
    gather_kernel<<<dim3((TOPK + 31) / 32, B), 256>>>(des_out);
}